// round 8
// baseline (speedup 1.0000x reference)
#include <cuda_runtime.h>
#include <cuda_bf16.h>
#include <cstdint>

#define B_ 8
#define N_ 200
#define D_ 128
#define BN_ (B_ * N_)            // 1600
#define HSZ (B_ * N_ * D_)       // 204800
#define ESZ (B_ * N_ * N_ * D_)  // 40960000
#define EPS 1e-5f
#define EBLKS (ESZ / 4 / 256)    // 40000
#define HBLKS (HSZ / 4 / 256)    // 200

// ---------------- scratch (device globals, no allocation) ----------------
__device__ float g_Uh[HSZ];
__device__ float g_Vh[HSZ];
__device__ float g_Ah[HSZ];
__device__ float g_Bh[HSZ];
__device__ float g_hnew[HSZ];
__device__ float g_acc[4 * D_];   // e_sum, e_sqsum, h_sum, h_sqsum
__device__ float g_coef[4 * D_];  // scale_e, shift_e, scale_h, shift_h
__device__ uint32_t g_CwH[D_ * 64];  // bf16-pair-packed Cw hi, [d][kword]
__device__ uint32_t g_CwL[D_ * 64];  // bf16-pair-packed Cw lo, [d][kword]
__device__ unsigned int g_done;

// ================= helpers ===========================================
__device__ __forceinline__ uint32_t pack_bf(float x, float y) {
    __nv_bfloat162 p = __floats2bfloat162_rn(x, y);
    return *reinterpret_cast<uint32_t*>(&p);
}

__device__ __forceinline__ void mma16816(float* c,
                                         uint32_t a0, uint32_t a1, uint32_t a2, uint32_t a3,
                                         uint32_t b0, uint32_t b1) {
    asm volatile(
        "mma.sync.aligned.m16n8k16.row.col.f32.bf16.bf16.f32 "
        "{%0,%1,%2,%3}, {%4,%5,%6,%7}, {%8,%9}, {%0,%1,%2,%3};"
        : "+f"(c[0]), "+f"(c[1]), "+f"(c[2]), "+f"(c[3])
        : "r"(a0), "r"(a1), "r"(a2), "r"(a3), "r"(b0), "r"(b1));
}

__device__ __forceinline__ void ldmx4(uint32_t& r0, uint32_t& r1, uint32_t& r2, uint32_t& r3,
                                      uint32_t saddr) {
    asm volatile("ldmatrix.sync.aligned.m8n8.x4.shared.b16 {%0,%1,%2,%3}, [%4];"
                 : "=r"(r0), "=r"(r1), "=r"(r2), "=r"(r3) : "r"(saddr));
}

__device__ __forceinline__ uint32_t smem_u32(const void* p) {
    uint32_t a;
    asm("{ .reg .u64 t; cvta.to.shared.u64 t, %1; cvt.u32.u64 %0, t; }" : "=r"(a) : "l"(p));
    return a;
}
#define CP_ASYNC16(dst, src) \
    asm volatile("cp.async.cg.shared.global [%0], [%1], 16;" :: "r"(dst), "l"(src))
#define CP_COMMIT() asm volatile("cp.async.commit_group;" ::: "memory")
#define CP_WAIT0() asm volatile("cp.async.wait_group 0;" ::: "memory")

// ---------------- K0: zero accumulators + pack Cw -------------------------
__global__ void setup_kernel(const float* __restrict__ Cw) {
    const int t = threadIdx.x;  // 512
    if (t < 4 * D_) g_acc[t] = 0.0f;
    if (t == 0) g_done = 0u;
    if (t < 128) {
        const int d = t;
        const float4* C4 = reinterpret_cast<const float4*>(Cw);
#pragma unroll 4
        for (int u = 0; u < 32; u++) {
            float4 v = C4[d * 32 + u];
            float hx = __bfloat162float(__float2bfloat16(v.x));
            float hy = __bfloat162float(__float2bfloat16(v.y));
            float hz = __bfloat162float(__float2bfloat16(v.z));
            float hw = __bfloat162float(__float2bfloat16(v.w));
            g_CwH[d * 64 + 2 * u + 0] = pack_bf(hx, hy);
            g_CwH[d * 64 + 2 * u + 1] = pack_bf(hz, hw);
            g_CwL[d * 64 + 2 * u + 0] = pack_bf(v.x - hx, v.y - hy);
            g_CwL[d * 64 + 2 * u + 1] = pack_bf(v.z - hz, v.w - hw);
        }
    }
}

// ---------------- K1: four projections  Xh = h @ Xw^T + Xb ----------------
__global__ void proj_kernel(const float* __restrict__ h,
                            const float* __restrict__ Uw, const float* __restrict__ Ub,
                            const float* __restrict__ Vw, const float* __restrict__ Vb,
                            const float* __restrict__ Aw, const float* __restrict__ Ab,
                            const float* __restrict__ Bw, const float* __restrict__ Bb) {
    extern __shared__ float sm[];
    float* hs = sm;              // 8*128
    float* wt = sm + 1024;       // 128*129
    const int tid = threadIdx.x;
    const int row0 = blockIdx.x * 8;

#pragma unroll
    for (int r = 0; r < 8; r++) hs[r * D_ + tid] = h[(row0 + r) * D_ + tid];

    const float* Ws[4] = {Uw, Vw, Aw, Bw};
    const float* bs[4] = {Ub, Vb, Ab, Bb};
    float* outs[4] = {g_Uh, g_Vh, g_Ah, g_Bh};

    for (int m = 0; m < 4; m++) {
        __syncthreads();
        const float4* W4 = reinterpret_cast<const float4*>(Ws[m]);
#pragma unroll
        for (int t = 0; t < 32; t++) {
            int idx4 = t * 128 + tid;
            float4 v = W4[idx4];
            int d = idx4 >> 5;
            int k = (idx4 & 31) << 2;
            wt[(k + 0) * 129 + d] = v.x;
            wt[(k + 1) * 129 + d] = v.y;
            wt[(k + 2) * 129 + d] = v.z;
            wt[(k + 3) * 129 + d] = v.w;
        }
        __syncthreads();

        float acc[8] = {0, 0, 0, 0, 0, 0, 0, 0};
        for (int k = 0; k < D_; k++) {
            float w = wt[k * 129 + tid];
#pragma unroll
            for (int r = 0; r < 8; r++) acc[r] += hs[r * D_ + k] * w;
        }
        float bias = bs[m][tid];
#pragma unroll
        for (int r = 0; r < 8; r++)
            outs[m][(row0 + r) * D_ + tid] = acc[r] + bias;
    }
}

// smem word-layout constants for fuse
#define E_STRIDE 68     // words per j-row of e tiles (64 + 4 pad)
#define CWL_STRIDE 68   // words per d-row of Cw-lo tile
#define CWL_OFF 0                        // 128*68 = 8704 words
#define RAW_OFF 8704                     // 64*128 = 8192 words (raw fp32 e tile)
#define EHI_OFF (8704 + 8192)            // 16896; 64*68 = 4352 words
#define ELO_OFF (16896 + 4352)           // 21248
#define RED_OFF (16896 + 2 * 4352)       // 25600, 384 floats
#define FUSE_WORDS (25600 + 384)         // 25984 words = 103936 B

// ldmatrix-based mma over one j-tile. NT = number of 8-row j-groups (8 or 1).
template <int NT>
__device__ __forceinline__ void mma_tile(uint32_t cwl_s, uint32_t ehi_s, uint32_t elo_s,
                                         float acc[8][4], const uint32_t a_hi[8][4],
                                         uint32_t aw0, uint32_t bw0) {
#pragma unroll
    for (int ks = 0; ks < 8; ks++) {
        uint32_t al0, al1, al2, al3;
        ldmx4(al0, al1, al2, al3, cwl_s + (aw0 + 8 * ks) * 4);
#pragma unroll
        for (int nt2 = 0; nt2 < NT; nt2 += 2) {
            const uint32_t boff = (bw0 + nt2 * 8 * E_STRIDE + 8 * ks) * 4;
            uint32_t bh0a, bh1a, bh0b, bh1b, bl0a, bl1a, bl0b, bl1b;
            ldmx4(bh0a, bh1a, bh0b, bh1b, ehi_s + boff);
            ldmx4(bl0a, bl1a, bl0b, bl1b, elo_s + boff);
            mma16816(acc[nt2], a_hi[ks][0], a_hi[ks][1], a_hi[ks][2], a_hi[ks][3], bh0a, bh1a);
            mma16816(acc[nt2], al0, al1, al2, al3, bh0a, bh1a);
            mma16816(acc[nt2], a_hi[ks][0], a_hi[ks][1], a_hi[ks][2], a_hi[ks][3], bl0a, bl1a);
            if (NT > 1) {
                mma16816(acc[nt2 + 1], a_hi[ks][0], a_hi[ks][1], a_hi[ks][2], a_hi[ks][3], bh0b, bh1b);
                mma16816(acc[nt2 + 1], al0, al1, al2, al3, bh0b, bh1b);
                mma16816(acc[nt2 + 1], a_hi[ks][0], a_hi[ks][1], a_hi[ks][2], a_hi[ks][3], bl0b, bl1b);
            }
        }
    }
}

// ---------------- K2: mma.sync fused, register epilogue -------------------
// grid = 1600 blocks (one per (b,i)), 256 threads (8 warps).
// Thread fragment ownership: d in {warp*16+g, +8}, j in {8*nt+2*tig, +1}.
__global__ void __launch_bounds__(256, 2)
fuse_mma_kernel(const float* __restrict__ e,
                const float* __restrict__ Cb,
                float* __restrict__ e_new_out,
                const float* __restrict__ gamma_e, const float* __restrict__ beta_e,
                const float* __restrict__ gamma_h, const float* __restrict__ beta_h) {
    extern __shared__ uint32_t smw[];
    uint32_t* cwl = smw + CWL_OFF;
    float* raw = reinterpret_cast<float*>(smw + RAW_OFF);
    uint32_t* e_hi = smw + EHI_OFF;
    uint32_t* e_lo = smw + ELO_OFF;
    float* red = reinterpret_cast<float*>(smw + RED_OFF);
    __shared__ unsigned int s_ticket;

    const int tid = threadIdx.x;
    const int lane = tid & 31;
    const int warp = tid >> 5;     // 0..7
    const int g = lane >> 2;
    const int tig = lane & 3;
    const int arow = warp * 16 + g;       // this thread's low d
    const int role = lane >> 3;    // 0..3
    const int rr = lane & 7;       // row within ldmatrix matrix
    const int bi = blockIdx.x;
    const int b = bi / N_;

    // ldmatrix per-thread base word offsets
    const uint32_t aw0 = (uint32_t)((warp * 16 + (role & 1) * 8 + rr) * CWL_STRIDE + (role >> 1) * 4);
    const uint32_t bw0 = (uint32_t)((8 * (role >> 1) + rr) * E_STRIDE + (role & 1) * 4);

    const float* e_base = e + (size_t)bi * N_ * D_;
    const uint32_t raw_s = smem_u32(raw);
    const uint32_t cwl_s = smem_u32(cwl);
    const uint32_t ehi_s = smem_u32(e_hi);
    const uint32_t elo_s = smem_u32(e_lo);

    // ---- prologue: async-stage raw tile 0, then setup ----
    {
        const float4* E4 = reinterpret_cast<const float4*>(e_base);
#pragma unroll
        for (int u = 0; u < 8; u++) {
            int fid = tid + u * 256;
            CP_ASYNC16(raw_s + fid * 16, (const char*)(E4 + fid));
        }
        CP_COMMIT();
    }

    for (int w = tid; w < D_ * 64; w += 256) {
        cwl[(w >> 6) * CWL_STRIDE + (w & 63)] = g_CwL[w];
    }
    uint32_t a_hi[8][4];
#pragma unroll
    for (int ks = 0; ks < 8; ks++) {
        a_hi[ks][0] = g_CwH[arow * 64 + 8 * ks + tig];
        a_hi[ks][1] = g_CwH[(arow + 8) * 64 + 8 * ks + tig];
        a_hi[ks][2] = g_CwH[arow * 64 + 8 * ks + tig + 4];
        a_hi[ks][3] = g_CwH[(arow + 8) * 64 + 8 * ks + tig + 4];
    }

    float* eo_base = e_new_out + (size_t)bi * N_ * D_;
    const float* Ah_b = g_Ah + (size_t)b * N_ * D_;
    const float* Vh_b = g_Vh + (size_t)b * N_ * D_;
    const float BhA = g_Bh[(size_t)bi * D_ + arow];
    const float BhB = g_Bh[(size_t)bi * D_ + arow + 8];
    const float CbA = Cb[arow];
    const float CbB = Cb[arow + 8];

    // per-thread stats for d = arow (A) and arow+8 (B)
    float sA = 0.f, sqA = 0.f, agA = 0.f;
    float sB = 0.f, sqB = 0.f, agB = 0.f;

    CP_WAIT0();
    __syncthreads();

    for (int tile = 0; tile < 4; tile++) {
        const int j0 = tile * 64;
        const int jcnt = (tile < 3) ? 64 : (N_ - 192);   // 64,64,64,8
        const int NTm = (tile < 3) ? 8 : 1;

        // ---- convert raw -> bf16 hi/lo pairs (smem -> smem) ----
        {
            const int nf4 = jcnt * 32;
            for (int fid = tid; fid < nf4; fid += 256) {
                int row = fid >> 5;
                int k4 = fid & 31;
                float4 v = *reinterpret_cast<const float4*>(&raw[fid * 4]);
                float hx = __bfloat162float(__float2bfloat16(v.x));
                float hy = __bfloat162float(__float2bfloat16(v.y));
                float hz = __bfloat162float(__float2bfloat16(v.z));
                float hw = __bfloat162float(__float2bfloat16(v.w));
                int wofs = row * E_STRIDE + 2 * k4;
                *reinterpret_cast<uint2*>(&e_hi[wofs]) =
                    make_uint2(pack_bf(hx, hy), pack_bf(hz, hw));
                *reinterpret_cast<uint2*>(&e_lo[wofs]) =
                    make_uint2(pack_bf(v.x - hx, v.y - hy), pack_bf(v.z - hz, v.w - hw));
            }
        }
        __syncthreads();   // e tiles ready; raw free

        // ---- async-stage next raw tile (overlaps mma + epilogue) ----
        if (tile < 3) {
            const int njcnt = (tile < 2) ? 64 : (N_ - 192);
            const int nnf4 = njcnt * 32;
            const float4* E4 = reinterpret_cast<const float4*>(e_base + (size_t)(j0 + 64) * D_);
            for (int fid = tid; fid < nnf4; fid += 256) {
                CP_ASYNC16(raw_s + fid * 16, (const char*)(E4 + fid));
            }
            CP_COMMIT();
        }

        // ---- mma ----
        float acc[8][4];
#pragma unroll
        for (int nt = 0; nt < 8; nt++)
#pragma unroll
            for (int q = 0; q < 4; q++) acc[nt][q] = 0.0f;

        if (tile < 3) {
            mma_tile<8>(cwl_s, ehi_s, elo_s, acc, a_hi, aw0, bw0);
        } else {
            mma_tile<1>(cwl_s, ehi_s, elo_s, acc, a_hi, aw0, bw0);
        }

        // ---- register epilogue (no smem round-trip) ----
#pragma unroll
        for (int nt = 0; nt < 8; nt++) {
            if (nt >= NTm) break;
            const int j = j0 + 8 * nt + 2 * tig;
            const float* Aj0 = Ah_b + (size_t)j * D_;
            const float* Vj0 = Vh_b + (size_t)j * D_;
            float a00 = Aj0[arow], a01 = Aj0[arow + 8];
            float a10 = Aj0[D_ + arow], a11 = Aj0[D_ + arow + 8];
            float v00 = Vj0[arow], v01 = Vj0[arow + 8];
            float v10 = Vj0[D_ + arow], v11 = Vj0[D_ + arow + 8];

            float x0 = acc[nt][0] + CbA + BhA + a00;
            float x1 = acc[nt][1] + CbA + BhA + a10;
            float x2 = acc[nt][2] + CbB + BhB + a01;
            float x3 = acc[nt][3] + CbB + BhB + a11;

            float* Ej0 = eo_base + (size_t)j * D_;
            Ej0[arow] = x0;
            Ej0[D_ + arow] = x1;
            Ej0[arow + 8] = x2;
            Ej0[D_ + arow + 8] = x3;

            sA += x0 + x1;
            sqA += x0 * x0 + x1 * x1;
            sB += x2 + x3;
            sqB += x2 * x2 + x3 * x3;
            agA += __fdividef(v00, 1.0f + __expf(-x0)) + __fdividef(v10, 1.0f + __expf(-x1));
            agB += __fdividef(v01, 1.0f + __expf(-x2)) + __fdividef(v11, 1.0f + __expf(-x3));
        }

        CP_WAIT0();
        __syncthreads();   // mma reads done + raw(t+1) ready before next convert
    }

    // ---- reduce across tig lanes (disjoint j, same d) ----
#pragma unroll
    for (int m = 1; m <= 2; m <<= 1) {
        sA += __shfl_xor_sync(0xFFFFFFFFu, sA, m);
        sqA += __shfl_xor_sync(0xFFFFFFFFu, sqA, m);
        agA += __shfl_xor_sync(0xFFFFFFFFu, agA, m);
        sB += __shfl_xor_sync(0xFFFFFFFFu, sB, m);
        sqB += __shfl_xor_sync(0xFFFFFFFFu, sqB, m);
        agB += __shfl_xor_sync(0xFFFFFFFFu, agB, m);
    }
    if (tig == 0) {   // each (warp,g) owns unique d pair -> no atomics
        red[arow] = agA;
        red[arow + 8] = agB;
        red[128 + arow] = sA;
        red[128 + arow + 8] = sB;
        red[256 + arow] = sqA;
        red[256 + arow + 8] = sqB;
    }
    __syncthreads();

    if (tid < 128) {
        const int d = tid;
        float hn = g_Uh[(size_t)bi * D_ + d] + red[d];
        g_hnew[(size_t)bi * D_ + d] = hn;
        atomicAdd(&g_acc[0 * D_ + d], red[128 + d]);
        atomicAdd(&g_acc[1 * D_ + d], red[256 + d]);
        atomicAdd(&g_acc[2 * D_ + d], hn);
        atomicAdd(&g_acc[3 * D_ + d], hn * hn);
    }

    // ---- last block computes BN coefficients (fused finalize) ----
    __threadfence();
    __syncthreads();
    if (tid == 0) s_ticket = atomicAdd(&g_done, 1u);
    __syncthreads();
    if (s_ticket == BN_ - 1 && tid < 128) {
        const int d = tid;
        const float Ne = (float)B_ * N_ * N_;
        float mu = g_acc[d] / Ne;
        float var = g_acc[D_ + d] / Ne - mu * mu;
        float sc = rsqrtf(var + EPS) * gamma_e[d];
        g_coef[d] = sc;
        g_coef[D_ + d] = beta_e[d] - mu * sc;

        const float Nh = (float)B_ * N_;
        float muh = g_acc[2 * D_ + d] / Nh;
        float varh = g_acc[3 * D_ + d] / Nh - muh * muh;
        float sch = rsqrtf(varh + EPS) * gamma_h[d];
        g_coef[2 * D_ + d] = sch;
        g_coef[3 * D_ + d] = beta_h[d] - muh * sch;
    }
}

// ---------------- K3: combined epilogue (e blocks then h blocks) ----------
__global__ void final_kernel(const float* __restrict__ e_in, const float* __restrict__ h_in,
                             float* __restrict__ e_out, float* __restrict__ h_out) {
    const int blk = blockIdx.x;
    if (blk < EBLKS) {
        size_t idx = (size_t)blk * 256 + threadIdx.x;
        int d4 = (int)(idx & 31);
        float4 sc = reinterpret_cast<const float4*>(g_coef)[d4];
        float4 sh = reinterpret_cast<const float4*>(g_coef + D_)[d4];
        float4 x = reinterpret_cast<const float4*>(e_out)[idx];
        float4 ei = reinterpret_cast<const float4*>(e_in)[idx];
        float4 r;
        r.x = ei.x + fmaxf(0.0f, x.x * sc.x + sh.x);
        r.y = ei.y + fmaxf(0.0f, x.y * sc.y + sh.y);
        r.z = ei.z + fmaxf(0.0f, x.z * sc.z + sh.z);
        r.w = ei.w + fmaxf(0.0f, x.w * sc.w + sh.w);
        reinterpret_cast<float4*>(e_out)[idx] = r;
    } else {
        size_t idx = (size_t)(blk - EBLKS) * 256 + threadIdx.x;
        int d4 = (int)(idx & 31);
        float4 sc = reinterpret_cast<const float4*>(g_coef + 2 * D_)[d4];
        float4 sh = reinterpret_cast<const float4*>(g_coef + 3 * D_)[d4];
        float4 x = reinterpret_cast<const float4*>(g_hnew)[idx];
        float4 hi = reinterpret_cast<const float4*>(h_in)[idx];
        float4 r;
        r.x = hi.x + fmaxf(0.0f, x.x * sc.x + sh.x);
        r.y = hi.y + fmaxf(0.0f, x.y * sc.y + sh.y);
        r.z = hi.z + fmaxf(0.0f, x.z * sc.z + sh.z);
        r.w = hi.w + fmaxf(0.0f, x.w * sc.w + sh.w);
        reinterpret_cast<float4*>(h_out)[idx] = r;
    }
}

// ---------------- launch ---------------------------------------------------
extern "C" void kernel_launch(void* const* d_in, const int* in_sizes, int n_in,
                              void* d_out, int out_size) {
    const float* h = (const float*)d_in[0];
    const float* e = (const float*)d_in[1];
    const float* Uw = (const float*)d_in[2];
    const float* Ub = (const float*)d_in[3];
    const float* Vw = (const float*)d_in[4];
    const float* Vb = (const float*)d_in[5];
    const float* Aw = (const float*)d_in[6];
    const float* Ab = (const float*)d_in[7];
    const float* Bw = (const float*)d_in[8];
    const float* Bb = (const float*)d_in[9];
    const float* Cw = (const float*)d_in[10];
    const float* Cb = (const float*)d_in[11];
    const float* gamma_h = (const float*)d_in[12];
    const float* beta_h = (const float*)d_in[13];
    const float* gamma_e = (const float*)d_in[14];
    const float* beta_e = (const float*)d_in[15];

    float* out = (float*)d_out;
    float* h_out = out;          // [B,N,D]
    float* e_out = out + HSZ;    // [B,N,N,D] (e_new scratch then final)

    static int attr_done = 0;
    const int proj_smem = (1024 + 16512) * 4;   // 70144 B
    const int fuse_smem = FUSE_WORDS * 4;       // 103936 B
    if (!attr_done) {
        cudaFuncSetAttribute(proj_kernel, cudaFuncAttributeMaxDynamicSharedMemorySize, proj_smem);
        cudaFuncSetAttribute(fuse_mma_kernel, cudaFuncAttributeMaxDynamicSharedMemorySize, fuse_smem);
        attr_done = 1;
    }

    setup_kernel<<<1, 512>>>(Cw);
    proj_kernel<<<BN_ / 8, 128, proj_smem>>>(h, Uw, Ub, Vw, Vb, Aw, Ab, Bw, Bb);
    fuse_mma_kernel<<<BN_, 256, fuse_smem>>>(e, Cb, e_out, gamma_e, beta_e, gamma_h, beta_h);
    final_kernel<<<EBLKS + HBLKS, 256>>>(e, h, e_out, h_out);
}

// round 9
// speedup vs baseline: 1.0315x; 1.0315x over previous
#include <cuda_runtime.h>
#include <cuda_bf16.h>
#include <cstdint>

#define B_ 8
#define N_ 200
#define D_ 128
#define BN_ (B_ * N_)            // 1600
#define HSZ (B_ * N_ * D_)       // 204800
#define ESZ (B_ * N_ * N_ * D_)  // 40960000
#define EPS 1e-5f
#define NBLK 296                 // 2 blocks/SM x 148 SMs, all co-resident

// ---------------- scratch (device globals, no allocation) ----------------
__device__ float g_Uh[HSZ];
__device__ float g_Vh[HSZ];
__device__ float g_Ah[HSZ];
__device__ float g_Bh[HSZ];
__device__ float g_hnew[HSZ];
__device__ float g_acc[4 * D_];   // e_sum, e_sqsum, h_sum, h_sqsum
__device__ float g_coef[4 * D_];  // scale_e, shift_e, scale_h, shift_h
__device__ uint32_t g_CwH[D_ * 64];  // bf16-pair-packed Cw hi, [d][kword]
__device__ uint32_t g_CwL[D_ * 64];  // bf16-pair-packed Cw lo, [d][kword]
__device__ unsigned int g_done;
__device__ unsigned int g_release;

// ================= helpers ===========================================
__device__ __forceinline__ uint32_t pack_bf(float x, float y) {
    __nv_bfloat162 p = __floats2bfloat162_rn(x, y);
    return *reinterpret_cast<uint32_t*>(&p);
}

__device__ __forceinline__ void mma16816(float* c,
                                         uint32_t a0, uint32_t a1, uint32_t a2, uint32_t a3,
                                         uint32_t b0, uint32_t b1) {
    asm volatile(
        "mma.sync.aligned.m16n8k16.row.col.f32.bf16.bf16.f32 "
        "{%0,%1,%2,%3}, {%4,%5,%6,%7}, {%8,%9}, {%0,%1,%2,%3};"
        : "+f"(c[0]), "+f"(c[1]), "+f"(c[2]), "+f"(c[3])
        : "r"(a0), "r"(a1), "r"(a2), "r"(a3), "r"(b0), "r"(b1));
}

__device__ __forceinline__ void ldmx4(uint32_t& r0, uint32_t& r1, uint32_t& r2, uint32_t& r3,
                                      uint32_t saddr) {
    asm volatile("ldmatrix.sync.aligned.m8n8.x4.shared.b16 {%0,%1,%2,%3}, [%4];"
                 : "=r"(r0), "=r"(r1), "=r"(r2), "=r"(r3) : "r"(saddr));
}

__device__ __forceinline__ uint32_t smem_u32(const void* p) {
    uint32_t a;
    asm("{ .reg .u64 t; cvta.to.shared.u64 t, %1; cvt.u32.u64 %0, t; }" : "=r"(a) : "l"(p));
    return a;
}
#define CP_ASYNC16(dst, src) \
    asm volatile("cp.async.cg.shared.global [%0], [%1], 16;" :: "r"(dst), "l"(src))
#define CP_COMMIT() asm volatile("cp.async.commit_group;" ::: "memory")
#define CP_WAIT0() asm volatile("cp.async.wait_group 0;" ::: "memory")

// ---------------- K0: zero accumulators + pack Cw -------------------------
__global__ void setup_kernel(const float* __restrict__ Cw) {
    const int t = threadIdx.x;  // 512
    if (t < 4 * D_) g_acc[t] = 0.0f;
    if (t == 0) { g_done = 0u; g_release = 0u; }
    if (t < 128) {
        const int d = t;
        const float4* C4 = reinterpret_cast<const float4*>(Cw);
#pragma unroll 4
        for (int u = 0; u < 32; u++) {
            float4 v = C4[d * 32 + u];
            float hx = __bfloat162float(__float2bfloat16(v.x));
            float hy = __bfloat162float(__float2bfloat16(v.y));
            float hz = __bfloat162float(__float2bfloat16(v.z));
            float hw = __bfloat162float(__float2bfloat16(v.w));
            g_CwH[d * 64 + 2 * u + 0] = pack_bf(hx, hy);
            g_CwH[d * 64 + 2 * u + 1] = pack_bf(hz, hw);
            g_CwL[d * 64 + 2 * u + 0] = pack_bf(v.x - hx, v.y - hy);
            g_CwL[d * 64 + 2 * u + 1] = pack_bf(v.z - hz, v.w - hw);
        }
    }
}

// ---------------- K1: four projections  Xh = h @ Xw^T + Xb ----------------
__global__ void proj_kernel(const float* __restrict__ h,
                            const float* __restrict__ Uw, const float* __restrict__ Ub,
                            const float* __restrict__ Vw, const float* __restrict__ Vb,
                            const float* __restrict__ Aw, const float* __restrict__ Ab,
                            const float* __restrict__ Bw, const float* __restrict__ Bb) {
    extern __shared__ float sm[];
    float* hs = sm;              // 8*128
    float* wt = sm + 1024;       // 128*129
    const int tid = threadIdx.x;
    const int row0 = blockIdx.x * 8;

#pragma unroll
    for (int r = 0; r < 8; r++) hs[r * D_ + tid] = h[(row0 + r) * D_ + tid];

    const float* Ws[4] = {Uw, Vw, Aw, Bw};
    const float* bs[4] = {Ub, Vb, Ab, Bb};
    float* outs[4] = {g_Uh, g_Vh, g_Ah, g_Bh};

    for (int m = 0; m < 4; m++) {
        __syncthreads();
        const float4* W4 = reinterpret_cast<const float4*>(Ws[m]);
#pragma unroll
        for (int t = 0; t < 32; t++) {
            int idx4 = t * 128 + tid;
            float4 v = W4[idx4];
            int d = idx4 >> 5;
            int k = (idx4 & 31) << 2;
            wt[(k + 0) * 129 + d] = v.x;
            wt[(k + 1) * 129 + d] = v.y;
            wt[(k + 2) * 129 + d] = v.z;
            wt[(k + 3) * 129 + d] = v.w;
        }
        __syncthreads();

        float acc[8] = {0, 0, 0, 0, 0, 0, 0, 0};
        for (int k = 0; k < D_; k++) {
            float w = wt[k * 129 + tid];
#pragma unroll
            for (int r = 0; r < 8; r++) acc[r] += hs[r * D_ + k] * w;
        }
        float bias = bs[m][tid];
#pragma unroll
        for (int r = 0; r < 8; r++)
            outs[m][(row0 + r) * D_ + tid] = acc[r] + bias;
    }
}

// smem word-layout constants for fuse
#define E_STRIDE 68     // words per j-row of e tiles (64 + 4 pad)
#define CWL_STRIDE 68   // words per d-row of Cw-lo tile
#define XS_STRIDE 132   // floats per j-row of x tile (128 + 4 pad)
#define CWL_OFF 0                        // 128*68 = 8704 words
#define RAW_OFF 8704                     // 64*128 = 8192 words (raw fp32 e tile)
#define EHI_OFF (8704 + 8192)            // 16896; 64*68 = 4352 words
#define ELO_OFF (16896 + 4352)           // 21248
#define RED_OFF (16896 + 2 * 4352)       // 25600, 384 floats
#define FUSE_WORDS (25600 + 384)         // 25984 words = 103936 B
// XS (64*132 = 8448 floats) overlays EHI..ELO region (8704 words)

// ldmatrix-based mma over one j-tile. NT = number of 8-row j-groups (8 or 1).
template <int NT>
__device__ __forceinline__ void mma_tile(uint32_t cwl_s, uint32_t ehi_s, uint32_t elo_s,
                                         float acc[8][4], const uint32_t a_hi[8][4],
                                         uint32_t aw0, uint32_t bw0) {
#pragma unroll
    for (int ks = 0; ks < 8; ks++) {
        uint32_t al0, al1, al2, al3;
        ldmx4(al0, al1, al2, al3, cwl_s + (aw0 + 8 * ks) * 4);
#pragma unroll
        for (int nt2 = 0; nt2 < NT; nt2 += 2) {
            const uint32_t boff = (bw0 + nt2 * 8 * E_STRIDE + 8 * ks) * 4;
            uint32_t bh0a, bh1a, bh0b, bh1b, bl0a, bl1a, bl0b, bl1b;
            ldmx4(bh0a, bh1a, bh0b, bh1b, ehi_s + boff);
            ldmx4(bl0a, bl1a, bl0b, bl1b, elo_s + boff);
            mma16816(acc[nt2], a_hi[ks][0], a_hi[ks][1], a_hi[ks][2], a_hi[ks][3], bh0a, bh1a);
            mma16816(acc[nt2], al0, al1, al2, al3, bh0a, bh1a);
            mma16816(acc[nt2], a_hi[ks][0], a_hi[ks][1], a_hi[ks][2], a_hi[ks][3], bl0a, bl1a);
            if (NT > 1) {
                mma16816(acc[nt2 + 1], a_hi[ks][0], a_hi[ks][1], a_hi[ks][2], a_hi[ks][3], bh0b, bh1b);
                mma16816(acc[nt2 + 1], al0, al1, al2, al3, bh0b, bh1b);
                mma16816(acc[nt2 + 1], a_hi[ks][0], a_hi[ks][1], a_hi[ks][2], a_hi[ks][3], bl0b, bl1b);
            }
        }
    }
}

template <int NT>
__device__ __forceinline__ void spill_tile(float* __restrict__ XS, const float acc[8][4],
                                           int arow, int g, int tig) {
#pragma unroll
    for (int nt = 0; nt < NT; nt++) {
        const int jr = 8 * nt + 2 * tig;
        XS[jr * XS_STRIDE + arow] = acc[nt][0];
        XS[(jr + 1) * XS_STRIDE + arow] = acc[nt][1];
        XS[jr * XS_STRIDE + arow + 8] = acc[nt][2];
        XS[(jr + 1) * XS_STRIDE + arow + 8] = acc[nt][3];
    }
}

// ---------------- K2: persistent fused kernel -----------------------------
// grid = NBLK blocks (all co-resident), 256 threads (8 warps).
// Phase 1: per owned (b,i): Ce GEMM (bf16x3 mma) + e_new + gates + agg + stats.
// Global ticket barrier; last block computes BN coefs; release.
// Phase 2: per owned (b,i) LIFO: e_out/h_out epilogue (x still L2-warm).
__global__ void __launch_bounds__(256, 2)
fuse_persist_kernel(const float* __restrict__ e,
                    const float* __restrict__ h_in,
                    const float* __restrict__ Cb,
                    float* __restrict__ e_out,   // x scratch then final e_out
                    float* __restrict__ h_out,
                    const float* __restrict__ gamma_e, const float* __restrict__ beta_e,
                    const float* __restrict__ gamma_h, const float* __restrict__ beta_h) {
    extern __shared__ uint32_t smw[];
    uint32_t* cwl = smw + CWL_OFF;
    float* raw = reinterpret_cast<float*>(smw + RAW_OFF);
    uint32_t* e_hi = smw + EHI_OFF;
    uint32_t* e_lo = smw + ELO_OFF;
    float* red = reinterpret_cast<float*>(smw + RED_OFF);
    float* XS = reinterpret_cast<float*>(smw + EHI_OFF);  // overlays e tiles
    __shared__ unsigned int s_ticket;

    const int tid = threadIdx.x;
    const int lane = tid & 31;
    const int warp = tid >> 5;     // 0..7
    const int g = lane >> 2;
    const int tig = lane & 3;
    const int arow = warp * 16 + g;
    const int role = lane >> 3;    // 0..3
    const int rr = lane & 7;
    const int blk = blockIdx.x;
    const int dcol = tid & 127;
    const int jh = tid >> 7;       // 0 or 1

    const uint32_t aw0 = (uint32_t)((warp * 16 + (role & 1) * 8 + rr) * CWL_STRIDE + (role >> 1) * 4);
    const uint32_t bw0 = (uint32_t)((8 * (role >> 1) + rr) * E_STRIDE + (role & 1) * 4);

    const uint32_t raw_s = smem_u32(raw);
    const uint32_t cwl_s = smem_u32(cwl);
    const uint32_t ehi_s = smem_u32(e_hi);
    const uint32_t elo_s = smem_u32(e_lo);

    // ---- one-time per block: stage Cw-lo + A-hi fragments ----
    {
        const float4* E4 = reinterpret_cast<const float4*>(e + (size_t)blk * N_ * D_);
#pragma unroll
        for (int u = 0; u < 8; u++) {
            int fid = tid + u * 256;
            CP_ASYNC16(raw_s + fid * 16, (const char*)(E4 + fid));
        }
        CP_COMMIT();
    }
    for (int w = tid; w < D_ * 64; w += 256) {
        cwl[(w >> 6) * CWL_STRIDE + (w & 63)] = g_CwL[w];
    }
    uint32_t a_hi[8][4];
#pragma unroll
    for (int ks = 0; ks < 8; ks++) {
        a_hi[ks][0] = g_CwH[arow * 64 + 8 * ks + tig];
        a_hi[ks][1] = g_CwH[(arow + 8) * 64 + 8 * ks + tig];
        a_hi[ks][2] = g_CwH[arow * 64 + 8 * ks + tig + 4];
        a_hi[ks][3] = g_CwH[(arow + 8) * 64 + 8 * ks + tig + 4];
    }
    const float CbA = Cb[dcol];

    // =================== PHASE 1: owned pairs ===================
    for (int bi = blk; bi < BN_; bi += NBLK) {
        const int b = bi / N_;
        const float* e_base = e + (size_t)bi * N_ * D_;
        float* eo_base = e_out + (size_t)bi * N_ * D_;
        const float* Ah_b = g_Ah + (size_t)b * N_ * D_;
        const float* Vh_b = g_Vh + (size_t)b * N_ * D_;
        const float Bh_r = g_Bh[(size_t)bi * D_ + dcol];

        if (bi != blk) {
            // stage tile 0 of this pair
            const float4* E4 = reinterpret_cast<const float4*>(e_base);
#pragma unroll
            for (int u = 0; u < 8; u++) {
                int fid = tid + u * 256;
                CP_ASYNC16(raw_s + fid * 16, (const char*)(E4 + fid));
            }
            CP_COMMIT();
        }
        __syncthreads();   // previous pair's red reads complete
        if (tid < 128) {
            red[tid] = 0.0f;
            red[128 + tid] = 0.0f;
            red[256 + tid] = 0.0f;
        }
        float sumv = 0.0f, sqv = 0.0f, aggv = 0.0f;
        CP_WAIT0();
        __syncthreads();   // raw(0) + red ready

        for (int tile = 0; tile < 4; tile++) {
            const int j0 = tile * 64;
            const int jcnt = (tile < 3) ? 64 : (N_ - 192);   // 64,64,64,8

            // convert raw -> bf16 hi/lo
            {
                const int nf4 = jcnt * 32;
                for (int fid = tid; fid < nf4; fid += 256) {
                    int row = fid >> 5;
                    int k4 = fid & 31;
                    float4 v = *reinterpret_cast<const float4*>(&raw[fid * 4]);
                    float hx = __bfloat162float(__float2bfloat16(v.x));
                    float hy = __bfloat162float(__float2bfloat16(v.y));
                    float hz = __bfloat162float(__float2bfloat16(v.z));
                    float hw = __bfloat162float(__float2bfloat16(v.w));
                    int wofs = row * E_STRIDE + 2 * k4;
                    *reinterpret_cast<uint2*>(&e_hi[wofs]) =
                        make_uint2(pack_bf(hx, hy), pack_bf(hz, hw));
                    *reinterpret_cast<uint2*>(&e_lo[wofs]) =
                        make_uint2(pack_bf(v.x - hx, v.y - hy), pack_bf(v.z - hz, v.w - hw));
                }
            }
            __syncthreads();

            if (tile < 3) {
                const int njcnt = (tile < 2) ? 64 : (N_ - 192);
                const int nnf4 = njcnt * 32;
                const float4* E4 = reinterpret_cast<const float4*>(e_base + (size_t)(j0 + 64) * D_);
                for (int fid = tid; fid < nnf4; fid += 256) {
                    CP_ASYNC16(raw_s + fid * 16, (const char*)(E4 + fid));
                }
                CP_COMMIT();
            }

            float acc[8][4];
#pragma unroll
            for (int nt = 0; nt < 8; nt++)
#pragma unroll
                for (int q = 0; q < 4; q++) acc[nt][q] = 0.0f;

            if (tile < 3) {
                mma_tile<8>(cwl_s, ehi_s, elo_s, acc, a_hi, aw0, bw0);
            } else {
                mma_tile<1>(cwl_s, ehi_s, elo_s, acc, a_hi, aw0, bw0);
            }
            __syncthreads();

            if (tile < 3) {
                spill_tile<8>(XS, acc, arow, g, tig);
            } else {
                spill_tile<1>(XS, acc, arow, g, tig);
            }
            __syncthreads();

            // coalesced column pass
            const int half = jcnt >> 1;
            if (half == 32) {
#pragma unroll
                for (int jj0 = 0; jj0 < 32; jj0 += 8) {
                    float xv[8], av[8], vv[8];
#pragma unroll
                    for (int u = 0; u < 8; u++) {
                        const int j = jh * 32 + jj0 + u;
                        xv[u] = XS[j * XS_STRIDE + dcol];
                        av[u] = Ah_b[(j0 + j) * D_ + dcol];
                        vv[u] = Vh_b[(j0 + j) * D_ + dcol];
                    }
#pragma unroll
                    for (int u = 0; u < 8; u++) {
                        const int j = jh * 32 + jj0 + u;
                        float x = xv[u] + CbA + Bh_r + av[u];
                        eo_base[(size_t)(j0 + j) * D_ + dcol] = x;
                        sumv += x;
                        sqv += x * x;
                        aggv += __fdividef(vv[u], 1.0f + __expf(-x));
                    }
                }
            } else {
                for (int jj = 0; jj < half; jj++) {
                    const int j = jh * half + jj;
                    float x = XS[j * XS_STRIDE + dcol] + CbA + Bh_r + Ah_b[(j0 + j) * D_ + dcol];
                    eo_base[(size_t)(j0 + j) * D_ + dcol] = x;
                    sumv += x;
                    sqv += x * x;
                    aggv += __fdividef(Vh_b[(j0 + j) * D_ + dcol], 1.0f + __expf(-x));
                }
            }
            CP_WAIT0();
            __syncthreads();
        }

        // per-pair reduction
        atomicAdd(&red[dcol], aggv);
        atomicAdd(&red[128 + dcol], sumv);
        atomicAdd(&red[256 + dcol], sqv);
        __syncthreads();
        if (tid < 128) {
            const int d = tid;
            float hn = g_Uh[(size_t)bi * D_ + d] + red[d];
            g_hnew[(size_t)bi * D_ + d] = hn;
            atomicAdd(&g_acc[0 * D_ + d], red[128 + d]);
            atomicAdd(&g_acc[1 * D_ + d], red[256 + d]);
            atomicAdd(&g_acc[2 * D_ + d], hn);
            atomicAdd(&g_acc[3 * D_ + d], hn * hn);
        }
    }

    // =================== global barrier + coefs ===================
    __threadfence();
    __syncthreads();
    if (tid == 0) s_ticket = atomicAdd(&g_done, 1u);
    __syncthreads();
    if (s_ticket == NBLK - 1) {
        if (tid < 128) {
            const int d = tid;
            const float Ne = (float)B_ * N_ * N_;
            float mu = g_acc[d] / Ne;
            float var = g_acc[D_ + d] / Ne - mu * mu;
            float sc = rsqrtf(var + EPS) * gamma_e[d];
            g_coef[d] = sc;
            g_coef[D_ + d] = beta_e[d] - mu * sc;

            const float Nh = (float)B_ * N_;
            float muh = g_acc[2 * D_ + d] / Nh;
            float varh = g_acc[3 * D_ + d] / Nh - muh * muh;
            float sch = rsqrtf(varh + EPS) * gamma_h[d];
            g_coef[2 * D_ + d] = sch;
            g_coef[3 * D_ + d] = beta_h[d] - muh * sch;
        }
        __threadfence();
        __syncthreads();
        if (tid == 0) atomicExch(&g_release, 1u);
    } else {
        if (tid == 0) {
            unsigned int v = 0u;
            do {
                __nanosleep(64);
                asm volatile("ld.global.cg.u32 %0, [%1];" : "=r"(v) : "l"(&g_release));
            } while (v == 0u);
        }
        __syncthreads();
    }

    // =================== PHASE 2: epilogue on own pairs (LIFO) =============
    const int d4 = tid & 31;
    const float4 scE = reinterpret_cast<const float4*>(g_coef)[d4];
    const float4 shE = reinterpret_cast<const float4*>(g_coef + D_)[d4];

    int npairs = 0;
    for (int bi = blk; bi < BN_; bi += NBLK) npairs++;
    for (int p = npairs - 1; p >= 0; p--) {
        const int bi = blk + p * NBLK;
        const size_t base4 = (size_t)bi * (N_ * D_ / 4);   // 6400 f4 per pair
        const float4* X4 = reinterpret_cast<const float4*>(e_out) + base4;
        const float4* EI = reinterpret_cast<const float4*>(e) + base4;
        float4* EO = reinterpret_cast<float4*>(e_out) + base4;
#pragma unroll 5
        for (int u = 0; u < 25; u++) {
            const int fid = tid + u * 256;
            float4 x = X4[fid];
            float4 ei = EI[fid];
            float4 r;
            r.x = ei.x + fmaxf(0.0f, x.x * scE.x + shE.x);
            r.y = ei.y + fmaxf(0.0f, x.y * scE.y + shE.y);
            r.z = ei.z + fmaxf(0.0f, x.z * scE.z + shE.z);
            r.w = ei.w + fmaxf(0.0f, x.w * scE.w + shE.w);
            EO[fid] = r;
        }
        // h epilogue for this pair (row bi): 32 f4
        if (tid < 32) {
            const float4 scH = reinterpret_cast<const float4*>(g_coef + 2 * D_)[tid];
            const float4 shH = reinterpret_cast<const float4*>(g_coef + 3 * D_)[tid];
            const int i4 = bi * 32 + tid;
            float4 x = reinterpret_cast<const float4*>(g_hnew)[i4];
            float4 hi = reinterpret_cast<const float4*>(h_in)[i4];
            float4 r;
            r.x = hi.x + fmaxf(0.0f, x.x * scH.x + shH.x);
            r.y = hi.y + fmaxf(0.0f, x.y * scH.y + shH.y);
            r.z = hi.z + fmaxf(0.0f, x.z * scH.z + shH.z);
            r.w = hi.w + fmaxf(0.0f, x.w * scH.w + shH.w);
            reinterpret_cast<float4*>(h_out)[i4] = r;
        }
    }
}

// ---------------- launch ---------------------------------------------------
extern "C" void kernel_launch(void* const* d_in, const int* in_sizes, int n_in,
                              void* d_out, int out_size) {
    const float* h = (const float*)d_in[0];
    const float* e = (const float*)d_in[1];
    const float* Uw = (const float*)d_in[2];
    const float* Ub = (const float*)d_in[3];
    const float* Vw = (const float*)d_in[4];
    const float* Vb = (const float*)d_in[5];
    const float* Aw = (const float*)d_in[6];
    const float* Ab = (const float*)d_in[7];
    const float* Bw = (const float*)d_in[8];
    const float* Bb = (const float*)d_in[9];
    const float* Cw = (const float*)d_in[10];
    const float* Cb = (const float*)d_in[11];
    const float* gamma_h = (const float*)d_in[12];
    const float* beta_h = (const float*)d_in[13];
    const float* gamma_e = (const float*)d_in[14];
    const float* beta_e = (const float*)d_in[15];

    float* out = (float*)d_out;
    float* h_out = out;          // [B,N,D]
    float* e_out = out + HSZ;    // [B,N,N,D] (x scratch then final)

    static int attr_done = 0;
    const int proj_smem = (1024 + 16512) * 4;   // 70144 B
    const int fuse_smem = FUSE_WORDS * 4;       // 103936 B
    if (!attr_done) {
        cudaFuncSetAttribute(proj_kernel, cudaFuncAttributeMaxDynamicSharedMemorySize, proj_smem);
        cudaFuncSetAttribute(fuse_persist_kernel, cudaFuncAttributeMaxDynamicSharedMemorySize, fuse_smem);
        attr_done = 1;
    }

    setup_kernel<<<1, 512>>>(Cw);
    proj_kernel<<<BN_ / 8, 128, proj_smem>>>(h, Uw, Ub, Vw, Vb, Aw, Ab, Bw, Bb);
    fuse_persist_kernel<<<NBLK, 256, fuse_smem>>>(e, h, Cb, e_out, h_out,
                                                  gamma_e, beta_e, gamma_h, beta_h);
}

// round 12
// speedup vs baseline: 1.1510x; 1.1158x over previous
#include <cuda_runtime.h>
#include <cuda_bf16.h>
#include <cuda_fp16.h>
#include <cstdint>

#define B_ 8
#define N_ 200
#define D_ 128
#define BN_ (B_ * N_)            // 1600
#define HSZ (B_ * N_ * D_)       // 204800
#define ESZ (B_ * N_ * N_ * D_)  // 40960000
#define EPS 1e-5f
#define EBLKS (ESZ / 4 / 256)    // 40000
#define HBLKS (HSZ / 4 / 256)    // 200

// ---------------- scratch (device globals, no allocation) ----------------
__device__ float g_Uh[HSZ];
__device__ float g_Vh[HSZ];
__device__ float g_Ah[HSZ];
__device__ float g_Bh[HSZ];
__device__ float g_hnew[HSZ];
__device__ __align__(16) __half g_x[ESZ];   // fp16 e_new scratch (82 MB)
__device__ float g_acc[4 * D_];   // e_sum, e_sqsum, h_sum, h_sqsum
__device__ float g_coef[4 * D_];  // scale_e, shift_e, scale_h, shift_h
__device__ uint32_t g_CwH[D_ * 64];  // bf16-pair-packed Cw hi, [d][kword]
__device__ uint32_t g_CwL[D_ * 64];  // bf16-pair-packed Cw lo, [d][kword]
__device__ unsigned int g_done;

// ================= helpers ===========================================
__device__ __forceinline__ uint32_t pack_bf(float x, float y) {
    __nv_bfloat162 p = __floats2bfloat162_rn(x, y);
    return *reinterpret_cast<uint32_t*>(&p);
}

__device__ __forceinline__ void mma16816(float* c,
                                         uint32_t a0, uint32_t a1, uint32_t a2, uint32_t a3,
                                         uint32_t b0, uint32_t b1) {
    asm volatile(
        "mma.sync.aligned.m16n8k16.row.col.f32.bf16.bf16.f32 "
        "{%0,%1,%2,%3}, {%4,%5,%6,%7}, {%8,%9}, {%0,%1,%2,%3};"
        : "+f"(c[0]), "+f"(c[1]), "+f"(c[2]), "+f"(c[3])
        : "r"(a0), "r"(a1), "r"(a2), "r"(a3), "r"(b0), "r"(b1));
}

__device__ __forceinline__ void ldmx4(uint32_t& r0, uint32_t& r1, uint32_t& r2, uint32_t& r3,
                                      uint32_t saddr) {
    asm volatile("ldmatrix.sync.aligned.m8n8.x4.shared.b16 {%0,%1,%2,%3}, [%4];"
                 : "=r"(r0), "=r"(r1), "=r"(r2), "=r"(r3) : "r"(saddr));
}

__device__ __forceinline__ uint32_t smem_u32(const void* p) {
    uint32_t a;
    asm("{ .reg .u64 t; cvta.to.shared.u64 t, %1; cvt.u32.u64 %0, t; }" : "=r"(a) : "l"(p));
    return a;
}
#define CP_ASYNC16(dst, src) \
    asm volatile("cp.async.cg.shared.global [%0], [%1], 16;" :: "r"(dst), "l"(src))
#define CP_COMMIT() asm volatile("cp.async.commit_group;" ::: "memory")
#define CP_WAIT0() asm volatile("cp.async.wait_group 0;" ::: "memory")

// ---------------- K0: zero accumulators + pack Cw (parallel) --------------
// grid = 17 blocks x 256: blocks 0..15 pack Cw (4096 float4), block 16 zeroes.
__global__ void setup_kernel(const float* __restrict__ Cw) {
    if (blockIdx.x == 16) {
        for (int t = threadIdx.x; t < 4 * D_; t += 256) g_acc[t] = 0.0f;  // ALL 512
        if (threadIdx.x == 0) g_done = 0u;
        return;
    }
    const int gid = blockIdx.x * 256 + threadIdx.x;   // 0..4095
    const int d = gid >> 5;
    const int t = gid & 31;
    const float4 v = reinterpret_cast<const float4*>(Cw)[gid];
    float hx = __bfloat162float(__float2bfloat16(v.x));
    float hy = __bfloat162float(__float2bfloat16(v.y));
    float hz = __bfloat162float(__float2bfloat16(v.z));
    float hw = __bfloat162float(__float2bfloat16(v.w));
    g_CwH[d * 64 + 2 * t + 0] = pack_bf(hx, hy);
    g_CwH[d * 64 + 2 * t + 1] = pack_bf(hz, hw);
    g_CwL[d * 64 + 2 * t + 0] = pack_bf(v.x - hx, v.y - hy);
    g_CwL[d * 64 + 2 * t + 1] = pack_bf(v.z - hz, v.w - hw);
}

// ---------------- K1: four projections  Xh = h @ Xw^T + Xb ----------------
__global__ void proj_kernel(const float* __restrict__ h,
                            const float* __restrict__ Uw, const float* __restrict__ Ub,
                            const float* __restrict__ Vw, const float* __restrict__ Vb,
                            const float* __restrict__ Aw, const float* __restrict__ Ab,
                            const float* __restrict__ Bw, const float* __restrict__ Bb) {
    extern __shared__ float sm[];
    float* hs = sm;              // 8*128
    float* wt = sm + 1024;       // 128*129
    const int tid = threadIdx.x;
    const int row0 = blockIdx.x * 8;

#pragma unroll
    for (int r = 0; r < 8; r++) hs[r * D_ + tid] = h[(row0 + r) * D_ + tid];

    const float* Ws[4] = {Uw, Vw, Aw, Bw};
    const float* bs[4] = {Ub, Vb, Ab, Bb};
    float* outs[4] = {g_Uh, g_Vh, g_Ah, g_Bh};

    for (int m = 0; m < 4; m++) {
        __syncthreads();
        const float4* W4 = reinterpret_cast<const float4*>(Ws[m]);
#pragma unroll
        for (int t = 0; t < 32; t++) {
            int idx4 = t * 128 + tid;
            float4 v = W4[idx4];
            int d = idx4 >> 5;
            int k = (idx4 & 31) << 2;
            wt[(k + 0) * 129 + d] = v.x;
            wt[(k + 1) * 129 + d] = v.y;
            wt[(k + 2) * 129 + d] = v.z;
            wt[(k + 3) * 129 + d] = v.w;
        }
        __syncthreads();

        float acc[8] = {0, 0, 0, 0, 0, 0, 0, 0};
        for (int k = 0; k < D_; k++) {
            float w = wt[k * 129 + tid];
#pragma unroll
            for (int r = 0; r < 8; r++) acc[r] += hs[r * D_ + k] * w;
        }
        float bias = bs[m][tid];
#pragma unroll
        for (int r = 0; r < 8; r++)
            outs[m][(row0 + r) * D_ + tid] = acc[r] + bias;
    }
}

// smem word-layout constants for fuse
#define E_STRIDE 68     // words per j-row of e tiles (64 + 4 pad)
#define CWL_STRIDE 68   // words per d-row of Cw-lo tile
#define XS_STRIDE 132   // floats per j-row of x tile (128 + 4 pad)
#define CWL_OFF 0                        // 128*68 = 8704 words
#define RAW_OFF 8704                     // 64*128 = 8192 words (raw fp32 e tile)
#define EHI_OFF (8704 + 8192)            // 16896; 64*68 = 4352 words
#define ELO_OFF (16896 + 4352)           // 21248
#define RED_OFF (16896 + 2 * 4352)       // 25600, 384 floats
#define FUSE_WORDS (25600 + 384)         // 25984 words = 103936 B
// XS (64*132 = 8448 floats) overlays EHI..ELO region (8704 words)

// ldmatrix-based mma over one j-tile. NT = number of 8-row j-groups (8 or 1).
template <int NT>
__device__ __forceinline__ void mma_tile(uint32_t cwl_s, uint32_t ehi_s, uint32_t elo_s,
                                         float acc[8][4], const uint32_t a_hi[8][4],
                                         uint32_t aw0, uint32_t bw0) {
#pragma unroll
    for (int ks = 0; ks < 8; ks++) {
        uint32_t al0, al1, al2, al3;
        ldmx4(al0, al1, al2, al3, cwl_s + (aw0 + 8 * ks) * 4);
#pragma unroll
        for (int nt2 = 0; nt2 < NT; nt2 += 2) {
            const uint32_t boff = (bw0 + nt2 * 8 * E_STRIDE + 8 * ks) * 4;
            uint32_t bh0a, bh1a, bh0b, bh1b, bl0a, bl1a, bl0b, bl1b;
            ldmx4(bh0a, bh1a, bh0b, bh1b, ehi_s + boff);
            ldmx4(bl0a, bl1a, bl0b, bl1b, elo_s + boff);
            mma16816(acc[nt2], a_hi[ks][0], a_hi[ks][1], a_hi[ks][2], a_hi[ks][3], bh0a, bh1a);
            mma16816(acc[nt2], al0, al1, al2, al3, bh0a, bh1a);
            mma16816(acc[nt2], a_hi[ks][0], a_hi[ks][1], a_hi[ks][2], a_hi[ks][3], bl0a, bl1a);
            if (NT > 1) {
                mma16816(acc[nt2 + 1], a_hi[ks][0], a_hi[ks][1], a_hi[ks][2], a_hi[ks][3], bh0b, bh1b);
                mma16816(acc[nt2 + 1], al0, al1, al2, al3, bh0b, bh1b);
                mma16816(acc[nt2 + 1], a_hi[ks][0], a_hi[ks][1], a_hi[ks][2], a_hi[ks][3], bl0b, bl1b);
            }
        }
    }
}

template <int NT>
__device__ __forceinline__ void spill_tile(float* __restrict__ XS, const float acc[8][4],
                                           int arow, int g, int tig) {
#pragma unroll
    for (int nt = 0; nt < NT; nt++) {
        const int jr = 8 * nt + 2 * tig;
        XS[jr * XS_STRIDE + arow] = acc[nt][0];
        XS[(jr + 1) * XS_STRIDE + arow] = acc[nt][1];
        XS[jr * XS_STRIDE + arow + 8] = acc[nt][2];
        XS[(jr + 1) * XS_STRIDE + arow + 8] = acc[nt][3];
    }
}

// ---------------- K2: mma.sync fused, cp.async + ldmatrix, fp16 x out -----
// grid = 1600 blocks (one per (b,i)), 256 threads (8 warps).
__global__ void __launch_bounds__(256, 2)
fuse_mma_kernel(const float* __restrict__ e,
                const float* __restrict__ Cb,
                const float* __restrict__ gamma_e, const float* __restrict__ beta_e,
                const float* __restrict__ gamma_h, const float* __restrict__ beta_h) {
    extern __shared__ uint32_t smw[];
    uint32_t* cwl = smw + CWL_OFF;
    float* raw = reinterpret_cast<float*>(smw + RAW_OFF);
    uint32_t* e_hi = smw + EHI_OFF;
    uint32_t* e_lo = smw + ELO_OFF;
    float* red = reinterpret_cast<float*>(smw + RED_OFF);
    float* XS = reinterpret_cast<float*>(smw + EHI_OFF);  // overlays e tiles
    __shared__ unsigned int s_ticket;

    const int tid = threadIdx.x;
    const int lane = tid & 31;
    const int warp = tid >> 5;     // 0..7
    const int g = lane >> 2;
    const int tig = lane & 3;
    const int arow = warp * 16 + g;
    const int role = lane >> 3;    // 0..3
    const int rr = lane & 7;
    const int bi = blockIdx.x;
    const int b = bi / N_;
    const int dcol = tid & 127;
    const int jh = tid >> 7;       // 0 or 1

    const uint32_t aw0 = (uint32_t)((warp * 16 + (role & 1) * 8 + rr) * CWL_STRIDE + (role >> 1) * 4);
    const uint32_t bw0 = (uint32_t)((8 * (role >> 1) + rr) * E_STRIDE + (role & 1) * 4);

    const float* e_base = e + (size_t)bi * N_ * D_;
    const uint32_t raw_s = smem_u32(raw);
    const uint32_t cwl_s = smem_u32(cwl);
    const uint32_t ehi_s = smem_u32(e_hi);
    const uint32_t elo_s = smem_u32(e_lo);

    // ---- prologue: async-stage raw tile 0, then setup ----
    {
        const float4* E4 = reinterpret_cast<const float4*>(e_base);
#pragma unroll
        for (int u = 0; u < 8; u++) {
            int fid = tid + u * 256;
            CP_ASYNC16(raw_s + fid * 16, (const char*)(E4 + fid));
        }
        CP_COMMIT();
    }

    if (tid < 128) {
        red[tid] = 0.0f;
        red[128 + tid] = 0.0f;
        red[256 + tid] = 0.0f;
    }
    for (int w = tid; w < D_ * 64; w += 256) {
        cwl[(w >> 6) * CWL_STRIDE + (w & 63)] = g_CwL[w];
    }
    uint32_t a_hi[8][4];
#pragma unroll
    for (int ks = 0; ks < 8; ks++) {
        a_hi[ks][0] = g_CwH[arow * 64 + 8 * ks + tig];
        a_hi[ks][1] = g_CwH[(arow + 8) * 64 + 8 * ks + tig];
        a_hi[ks][2] = g_CwH[arow * 64 + 8 * ks + tig + 4];
        a_hi[ks][3] = g_CwH[(arow + 8) * 64 + 8 * ks + tig + 4];
    }

    __half* xo_base = g_x + (size_t)bi * N_ * D_;
    const float* Ah_b = g_Ah + (size_t)b * N_ * D_;
    const float* Vh_b = g_Vh + (size_t)b * N_ * D_;
    const float Bh_r = g_Bh[(size_t)bi * D_ + dcol];
    const float Cb_r = Cb[dcol];

    float sumv = 0.0f, sqv = 0.0f, aggv = 0.0f;

    CP_WAIT0();
    __syncthreads();

    for (int tile = 0; tile < 4; tile++) {
        const int j0 = tile * 64;
        const int jcnt = (tile < 3) ? 64 : (N_ - 192);   // 64,64,64,8

        // ---- convert raw -> bf16 hi/lo pairs (smem -> smem) ----
        {
            const int nf4 = jcnt * 32;
            for (int fid = tid; fid < nf4; fid += 256) {
                int row = fid >> 5;
                int k4 = fid & 31;
                float4 v = *reinterpret_cast<const float4*>(&raw[fid * 4]);
                float hx = __bfloat162float(__float2bfloat16(v.x));
                float hy = __bfloat162float(__float2bfloat16(v.y));
                float hz = __bfloat162float(__float2bfloat16(v.z));
                float hw = __bfloat162float(__float2bfloat16(v.w));
                int wofs = row * E_STRIDE + 2 * k4;
                *reinterpret_cast<uint2*>(&e_hi[wofs]) =
                    make_uint2(pack_bf(hx, hy), pack_bf(hz, hw));
                *reinterpret_cast<uint2*>(&e_lo[wofs]) =
                    make_uint2(pack_bf(v.x - hx, v.y - hy), pack_bf(v.z - hz, v.w - hw));
            }
        }
        __syncthreads();

        // ---- async-stage next raw tile ----
        if (tile < 3) {
            const int njcnt = (tile < 2) ? 64 : (N_ - 192);
            const int nnf4 = njcnt * 32;
            const float4* E4 = reinterpret_cast<const float4*>(e_base + (size_t)(j0 + 64) * D_);
            for (int fid = tid; fid < nnf4; fid += 256) {
                CP_ASYNC16(raw_s + fid * 16, (const char*)(E4 + fid));
            }
            CP_COMMIT();
        }

        // ---- mma ----
        float acc[8][4];
#pragma unroll
        for (int nt = 0; nt < 8; nt++)
#pragma unroll
            for (int q = 0; q < 4; q++) acc[nt][q] = 0.0f;

        if (tile < 3) {
            mma_tile<8>(cwl_s, ehi_s, elo_s, acc, a_hi, aw0, bw0);
        } else {
            mma_tile<1>(cwl_s, ehi_s, elo_s, acc, a_hi, aw0, bw0);
        }
        __syncthreads();

        if (tile < 3) {
            spill_tile<8>(XS, acc, arow, g, tig);
        } else {
            spill_tile<1>(XS, acc, arow, g, tig);
        }
        __syncthreads();

        // ---- column pass: thread (dcol, jh), batched prefetch ----
        const int half = jcnt >> 1;
        if (half == 32) {
#pragma unroll
            for (int jj0 = 0; jj0 < 32; jj0 += 8) {
                float xv[8], av[8], vv[8];
#pragma unroll
                for (int u = 0; u < 8; u++) {
                    const int j = jh * 32 + jj0 + u;
                    xv[u] = XS[j * XS_STRIDE + dcol];
                    av[u] = Ah_b[(j0 + j) * D_ + dcol];
                    vv[u] = Vh_b[(j0 + j) * D_ + dcol];
                }
#pragma unroll
                for (int u = 0; u < 8; u++) {
                    const int j = jh * 32 + jj0 + u;
                    float x = xv[u] + Cb_r + Bh_r + av[u];
                    xo_base[(size_t)(j0 + j) * D_ + dcol] = __float2half_rn(x);
                    sumv += x;
                    sqv += x * x;
                    aggv += __fdividef(vv[u], 1.0f + __expf(-x));
                }
            }
        } else {
            for (int jj = 0; jj < half; jj++) {
                const int j = jh * half + jj;
                float x = XS[j * XS_STRIDE + dcol] + Cb_r + Bh_r + Ah_b[(j0 + j) * D_ + dcol];
                xo_base[(size_t)(j0 + j) * D_ + dcol] = __float2half_rn(x);
                sumv += x;
                sqv += x * x;
                aggv += __fdividef(Vh_b[(j0 + j) * D_ + dcol], 1.0f + __expf(-x));
            }
        }
        CP_WAIT0();
        __syncthreads();
    }

    // ---- merge the two j-halves, then one global update per d ----
    atomicAdd(&red[dcol], aggv);
    atomicAdd(&red[128 + dcol], sumv);
    atomicAdd(&red[256 + dcol], sqv);
    __syncthreads();

    if (tid < 128) {
        const int d = tid;
        float hn = g_Uh[(size_t)bi * D_ + d] + red[d];
        g_hnew[(size_t)bi * D_ + d] = hn;
        atomicAdd(&g_acc[0 * D_ + d], red[128 + d]);
        atomicAdd(&g_acc[1 * D_ + d], red[256 + d]);
        atomicAdd(&g_acc[2 * D_ + d], hn);
        atomicAdd(&g_acc[3 * D_ + d], hn * hn);
    }

    // ---- last block computes BN coefficients (fused finalize) ----
    __threadfence();
    __syncthreads();
    if (tid == 0) s_ticket = atomicAdd(&g_done, 1u);
    __syncthreads();
    if (s_ticket == BN_ - 1 && tid < 128) {
        const int d = tid;
        const float Ne = (float)B_ * N_ * N_;
        float mu = g_acc[d] / Ne;
        float var = g_acc[D_ + d] / Ne - mu * mu;
        float sc = rsqrtf(var + EPS) * gamma_e[d];
        g_coef[d] = sc;
        g_coef[D_ + d] = beta_e[d] - mu * sc;

        const float Nh = (float)B_ * N_;
        float muh = g_acc[2 * D_ + d] / Nh;
        float varh = g_acc[3 * D_ + d] / Nh - muh * muh;
        float sch = rsqrtf(varh + EPS) * gamma_h[d];
        g_coef[2 * D_ + d] = sch;
        g_coef[3 * D_ + d] = beta_h[d] - muh * sch;
    }
}

// ---------------- K3: combined epilogue (e blocks then h blocks) ----------
__global__ void final_kernel(const float* __restrict__ e_in, const float* __restrict__ h_in,
                             float* __restrict__ e_out, float* __restrict__ h_out) {
    const int blk = blockIdx.x;
    if (blk < EBLKS) {
        size_t idx = (size_t)blk * 256 + threadIdx.x;   // float4 index (4 elements)
        int d4 = (int)(idx & 31);
        float4 sc = reinterpret_cast<const float4*>(g_coef)[d4];
        float4 sh = reinterpret_cast<const float4*>(g_coef + D_)[d4];
        uint2 xraw = *(reinterpret_cast<const uint2*>(g_x) + idx);
        __half2 xh0 = *reinterpret_cast<__half2*>(&xraw.x);
        __half2 xh1 = *reinterpret_cast<__half2*>(&xraw.y);
        float4 ei = reinterpret_cast<const float4*>(e_in)[idx];
        float4 r;
        r.x = ei.x + fmaxf(0.0f, __low2float(xh0) * sc.x + sh.x);
        r.y = ei.y + fmaxf(0.0f, __high2float(xh0) * sc.y + sh.y);
        r.z = ei.z + fmaxf(0.0f, __low2float(xh1) * sc.z + sh.z);
        r.w = ei.w + fmaxf(0.0f, __high2float(xh1) * sc.w + sh.w);
        reinterpret_cast<float4*>(e_out)[idx] = r;
    } else {
        size_t idx = (size_t)(blk - EBLKS) * 256 + threadIdx.x;
        int d4 = (int)(idx & 31);
        float4 sc = reinterpret_cast<const float4*>(g_coef + 2 * D_)[d4];
        float4 sh = reinterpret_cast<const float4*>(g_coef + 3 * D_)[d4];
        float4 x = reinterpret_cast<const float4*>(g_hnew)[idx];
        float4 hi = reinterpret_cast<const float4*>(h_in)[idx];
        float4 r;
        r.x = hi.x + fmaxf(0.0f, x.x * sc.x + sh.x);
        r.y = hi.y + fmaxf(0.0f, x.y * sc.y + sh.y);
        r.z = hi.z + fmaxf(0.0f, x.z * sc.z + sh.z);
        r.w = hi.w + fmaxf(0.0f, x.w * sc.w + sh.w);
        reinterpret_cast<float4*>(h_out)[idx] = r;
    }
}

// ---------------- launch ---------------------------------------------------
extern "C" void kernel_launch(void* const* d_in, const int* in_sizes, int n_in,
                              void* d_out, int out_size) {
    const float* h = (const float*)d_in[0];
    const float* e = (const float*)d_in[1];
    const float* Uw = (const float*)d_in[2];
    const float* Ub = (const float*)d_in[3];
    const float* Vw = (const float*)d_in[4];
    const float* Vb = (const float*)d_in[5];
    const float* Aw = (const float*)d_in[6];
    const float* Ab = (const float*)d_in[7];
    const float* Bw = (const float*)d_in[8];
    const float* Bb = (const float*)d_in[9];
    const float* Cw = (const float*)d_in[10];
    const float* Cb = (const float*)d_in[11];
    const float* gamma_h = (const float*)d_in[12];
    const float* beta_h = (const float*)d_in[13];
    const float* gamma_e = (const float*)d_in[14];
    const float* beta_e = (const float*)d_in[15];

    float* out = (float*)d_out;
    float* h_out = out;          // [B,N,D]
    float* e_out = out + HSZ;    // [B,N,N,D]

    static int attr_done = 0;
    const int proj_smem = (1024 + 16512) * 4;   // 70144 B
    const int fuse_smem = FUSE_WORDS * 4;       // 103936 B
    if (!attr_done) {
        cudaFuncSetAttribute(proj_kernel, cudaFuncAttributeMaxDynamicSharedMemorySize, proj_smem);
        cudaFuncSetAttribute(fuse_mma_kernel, cudaFuncAttributeMaxDynamicSharedMemorySize, fuse_smem);
        attr_done = 1;
    }

    setup_kernel<<<17, 256>>>(Cw);
    proj_kernel<<<BN_ / 8, 128, proj_smem>>>(h, Uw, Ub, Vw, Vb, Aw, Ab, Bw, Bb);
    fuse_mma_kernel<<<BN_, 256, fuse_smem>>>(e, Cb, gamma_e, beta_e, gamma_h, beta_h);
    final_kernel<<<EBLKS + HBLKS, 256>>>(e, h, e_out, h_out);
}